// round 11
// baseline (speedup 1.0000x reference)
#include <cuda_runtime.h>
#include <cuda_bf16.h>
#include <cuda_fp16.h>
#include <cstdint>
#include <cstdio>

// ---------------- constants ----------------
#define BB   32
#define DD   512
#define HH   8
#define DHH  64
#define ABB  8
#define KK   10
#define SPD  1032
#define FFD  2048
#define LATD 16
#define MSEQ 1024
#define MTOT (BB*SPD)          // 33024 = 258*128

#define WB_PER_LAYER 3145728   // qkv 786432 + wo 262144 + w1 1048576 + w2 1048576

// ---------------- scratch (device globals; no allocation) ----------------
__device__ float  g_h   [(size_t)BB*SPD*DD];
__device__ __align__(16) __half g_hh  [(size_t)BB*SPD*DD];
__device__ __align__(16) __half g_qkvh[(size_t)BB*SPD*3*DD];
__device__ __align__(16) __half g_atth[(size_t)BB*SPD*DD];
__device__ __align__(16) __half g_tmph[(size_t)BB*SPD*DD];
__device__ __align__(16) __half g_ffh [(size_t)BB*SPD*FFD];
__device__ float  g_z   [BB*LATD];
__device__ float  g_seq [BB*2*MSEQ];
__device__ float  g_elbo_b[BB];
__device__ __align__(16) __half g_wb[(size_t)10*WB_PER_LAYER];

// ---------------- helpers ----------------
#define CPA(smaddr, gptr) \
    asm volatile("cp.async.cg.shared.global [%0], [%1], 16;" :: "r"(smaddr), "l"(gptr))
#define CPC()  asm volatile("cp.async.commit_group;" ::: "memory")
#define CPW1() asm volatile("cp.async.wait_group 1;" ::: "memory")

__device__ __forceinline__ void ldsm4(uint32_t* r, uint32_t addr)
{
    asm volatile("ldmatrix.sync.aligned.m8n8.x4.shared.b16 {%0,%1,%2,%3}, [%4];"
        : "=r"(r[0]), "=r"(r[1]), "=r"(r[2]), "=r"(r[3]) : "r"(addr));
}
__device__ __forceinline__ void mma_f16(float* d, const uint32_t* a, const uint32_t* b)
{
    asm volatile("mma.sync.aligned.m16n8k16.row.col.f32.f16.f16.f32 "
        "{%0,%1,%2,%3}, {%4,%5,%6,%7}, {%8,%9}, {%0,%1,%2,%3};"
        : "+f"(d[0]), "+f"(d[1]), "+f"(d[2]), "+f"(d[3])
        : "r"(a[0]), "r"(a[1]), "r"(a[2]), "r"(a[3]), "r"(b[0]), "r"(b[1]));
}

// smem geometry for gemm: XOR-swizzled 128B rows, 3-stage pipeline
#define TILEB  (128*128)            // 16384: 128 rows x 64 halves
#define BUFB   (2*TILEB)            // 32768: A, W
#define SM_BUF 1024
#define SMEM_GEMM (SM_BUF + 3*BUFB) // 99328

// ---------------- weight transpose to fp16: W[K,N] -> Wh[N,K], batched -------
__global__ void wconv(const float* __restrict__ W, __half* __restrict__ hi,
                      int K, int N, size_t win_str, size_t wout_str)
{
    __shared__ float t[32][33];
    const float* Wl = W + (size_t)blockIdx.z * win_str;
    __half* hl = hi + (size_t)blockIdx.z * wout_str;
    int k0 = blockIdx.y * 32, n0 = blockIdx.x * 32;
    int tx = threadIdx.x, ty = threadIdx.y;   // 32 x 8
#pragma unroll
    for (int i = 0; i < 32; i += 8)
        t[ty + i][tx] = Wl[(size_t)(k0 + ty + i) * N + n0 + tx];
    __syncthreads();
#pragma unroll
    for (int i = 0; i < 32; i += 8)
        hl[(size_t)(n0 + ty + i) * K + k0 + tx] = __float2half_rn(t[tx][ty + i]);
}

// ---------------- tensor-core GEMM (mma.sync fp16, swizzled, 3-stage) ---------
// C[M,N] = A @ W^T + bias.  A fp16 [M,Kd]; W fp16 [N,Kd].
// mode 1: fp16 out + relu.  mode 2: fp16 out.
__global__ void __launch_bounds__(256) gemm_tc(
    const __half* __restrict__ A, const __half* __restrict__ W,
    const float* __restrict__ bias, __half* __restrict__ C,
    int N, int Kd, int mode)
{
    extern __shared__ char smem[];
    const int tid = threadIdx.x;
    const int lane = tid & 31, wid = tid >> 5;
    const int wr = wid >> 2, wc = wid & 3;          // 2 x 4 warp grid
    const int m0 = blockIdx.y * 128, n0 = blockIdx.x * 128;

    uint32_t sb;
    asm("{ .reg .u64 t; cvta.to.shared.u64 t, %1; cvt.u32.u64 %0, t; }"
        : "=r"(sb) : "l"(smem));

    float* biasS = (float*)smem;
    if (tid < 128) biasS[tid] = bias[n0 + tid];

    const int CHK = Kd >> 6;

    // swizzled cp.async loader: row r (128B), nominal seg s -> seg s^(r&7)
#define LOAD_TILE(dstoff, gbase)                                                 \
    {                                                                            \
        _Pragma("unroll")                                                        \
        for (int it = 0; it < 4; it++) {                                         \
            int s = it*256 + tid;                                                \
            int r = s >> 3, seg = s & 7;                                         \
            const __half* gp = (gbase) + (size_t)r * Kd + seg*8;                 \
            CPA(sb + (dstoff) + r*128 + ((seg ^ (r & 7)) << 4), gp);             \
        }                                                                        \
    }

#define LOAD_CHUNK(buf, c)                                                       \
    {                                                                            \
        const __half* ao = A + (size_t)m0*Kd + (c)*64;                           \
        const __half* wo = W + (size_t)n0*Kd + (c)*64;                           \
        LOAD_TILE(SM_BUF + (buf)*BUFB + 0*TILEB, ao);                            \
        LOAD_TILE(SM_BUF + (buf)*BUFB + 1*TILEB, wo);                            \
        CPC();                                                                   \
    }

    LOAD_CHUNK(0, 0);
    LOAD_CHUNK(1, 1);

    float acc[4][4][4] = {};

    uint32_t arow[4], akey[4];
#pragma unroll
    for (int i = 0; i < 4; i++) {
        uint32_t ra = wr*64 + i*16 + (lane & 15);
        arow[i] = ra * 128;
        akey[i] = ra & 7;
    }
    const uint32_t ahi = lane >> 4;
    uint32_t brow[2], bkey[2];
#pragma unroll
    for (int g = 0; g < 2; g++) {
        uint32_t rb = wc*32 + g*16 + (lane >> 4)*8 + (lane & 7);
        brow[g] = rb * 128;
        bkey[g] = rb & 7;
    }
    const uint32_t bhi = (lane >> 3) & 1;

    int cb = 0;
    for (int c = 0; c < CHK; c++) {
        CPW1();
        __syncthreads();
        if (c + 2 < CHK) {
            int nb3 = cb + 2; if (nb3 >= 3) nb3 -= 3;
            LOAD_CHUNK(nb3, c + 2);
        } else {
            CPC();
        }
        uint32_t Bs = sb + SM_BUF + cb*BUFB;
#pragma unroll
        for (int ks = 0; ks < 4; ks++) {
            uint32_t ca = ks*2 + ahi;
            uint32_t cbn = ks*2 + bhi;
            uint32_t ar[4][4], br[2][4];
#pragma unroll
            for (int i = 0; i < 4; i++)
                ldsm4(ar[i], Bs + arow[i] + (((ca ^ akey[i])) << 4));
#pragma unroll
            for (int g = 0; g < 2; g++)
                ldsm4(br[g], Bs + TILEB + brow[g] + (((cbn ^ bkey[g])) << 4));
#pragma unroll
            for (int i = 0; i < 4; i++)
#pragma unroll
            for (int j = 0; j < 4; j++)
                mma_f16(acc[i][j], ar[i], &br[j >> 1][(j & 1)*2]);
        }
        cb = (cb + 1 == 3) ? 0 : cb + 1;
    }

    // epilogue (fp16 out)
#pragma unroll
    for (int i = 0; i < 4; i++) {
        int row = m0 + wr*64 + i*16 + (lane >> 2);
#pragma unroll
        for (int j = 0; j < 4; j++) {
            int col = n0 + wc*32 + j*8 + (lane & 3)*2;
            float b0 = biasS[col - n0], b1 = biasS[col - n0 + 1];
            float v00 = acc[i][j][0] + b0, v01 = acc[i][j][1] + b1;
            float v10 = acc[i][j][2] + b0, v11 = acc[i][j][3] + b1;
            if (mode == 1) {
                v00 = fmaxf(v00, 0.f); v01 = fmaxf(v01, 0.f);
                v10 = fmaxf(v10, 0.f); v11 = fmaxf(v11, 0.f);
            }
            *(__half2*)&C[(size_t)row * N + col]       = __floats2half2_rn(v00, v01);
            *(__half2*)&C[(size_t)(row + 8) * N + col] = __floats2half2_rn(v10, v11);
        }
    }
#undef LOAD_TILE
#undef LOAD_CHUNK
}

// ---------------- encoder embedding (writes h fp32 + fp16) ----------------
__global__ void embed_enc(const float* __restrict__ x, const float* __restrict__ Wd,
                          const float* __restrict__ bd, const float* __restrict__ emb)
{
    int idx = blockIdx.x * blockDim.x + threadIdx.x;
    if (idx >= BB*SPD*DD) return;
    int d = idx & 511;
    int s = (idx >> 9) % SPD;
    int b = idx / (SPD*DD);
    float v = 0.f;
    if (s < MSEQ + 1) {
        v = emb[s*DD + d];
        if (s > 0) {
            const float* xr = x + ((size_t)b*MSEQ + (s-1)) * 16;
            float acc = bd[d];
#pragma unroll
            for (int j = 0; j < 16; j++) acc += xr[j] * Wd[j*DD + d];
            v += acc;
        }
    }
    g_h[idx] = v;
    g_hh[idx] = __float2half_rn(v);
}

// ---------------- block-sparse attention (fp16 in/out, fp32 accumulate) -------
// K/V stored in 128B smem rows with 4B-word XOR swizzle: word w of row kk lives
// at w ^ (kk & 31). Column reads (score loop: lanes=kk) and row reads (AV loop:
// lanes=d2) are both conflict-free.
__global__ void attn_kernel(const __half* __restrict__ qkv, __half* __restrict__ out,
                            const int* __restrict__ rnd, int nb, int S)
{
    int n = blockIdx.x, h = blockIdx.y, b = blockIdx.z;
    int tid = threadIdx.x;

    __shared__ __half2 qs[8][34];
    __shared__ uint32_t ksw[80][32];
    __shared__ uint32_t vsw[80][32];
    __shared__ float sc[8][80];
    __shared__ int   sbidx[KK];
    __shared__ int   svalid[KK];
    __shared__ float kmaskadd[80];

    if (tid < KK) {
        int j = tid, idx, valid = 1;
        if (j < 2)       { idx = j; }
        else if (j < 7)  { int w = n + j - 4; valid = (w >= 0 && w < nb);
                           idx = min(max(w, 0), nb - 1); }
        else             { idx = rnd[n*3 + (j - 7)]; }
        sbidx[j]  = idx;
        svalid[j] = valid;
    }
    __syncthreads();
    if (tid < 80) {
        int j = tid >> 3, p = tid & 7;
        int tok = sbidx[j]*ABB + p;
        kmaskadd[tid] = (svalid[j] && tok < S) ? 0.f : -1e9f;
    }

    const __half* base = qkv + (size_t)b * SPD * (3*DD);
    if (tid < 128) {
        int p = tid >> 4, seg = tid & 15;
        uint2 v = *(const uint2*)(base + (size_t)(n*ABB + p)*(3*DD) + h*DHH + seg*4);
        *(uint2*)&qs[p][seg*2] = v;
    }
    // K/V gather: 8B global loads, swizzled 4B smem stores
    for (int e = tid; e < 80*16; e += 256) {
        int kk = e >> 4, seg = e & 15;
        int j = kk >> 3, p = kk & 7;
        int row = sbidx[j]*ABB + p;
        const __half* rp = base + (size_t)row*(3*DD) + h*DHH + seg*4;
        uint2 kv = *(const uint2*)(rp + DD);
        uint2 vv = *(const uint2*)(rp + 2*DD);
        int key = kk & 31;
        int w0 = (seg*2) ^ key, w1 = (seg*2 + 1) ^ key;
        ksw[kk][w0] = kv.x; ksw[kk][w1] = kv.y;
        vsw[kk][w0] = vv.x; vsw[kk][w1] = vv.y;
    }
    __syncthreads();

    for (int e = tid; e < 640; e += 256) {
        int qi = e / 80, kk = e % 80;
        int key = kk & 31;
        float s = 0.f;
#pragma unroll
        for (int d2 = 0; d2 < 32; d2++) {
            float2 a = __half22float2(qs[qi][d2]);
            float2 bb = __half22float2(__halves2half2(
                ((const __half2*)&ksw[kk][d2 ^ key])->x,
                ((const __half2*)&ksw[kk][d2 ^ key])->y));
            s += a.x*bb.x + a.y*bb.y;
        }
        sc[qi][kk] = s * 0.125f + kmaskadd[kk];
    }
    __syncthreads();

    int warp = tid >> 5, lane = tid & 31;
    if (warp < 8) {
        float v0 = sc[warp][lane];
        float v1 = sc[warp][lane + 32];
        float v2 = (lane < 16) ? sc[warp][lane + 64] : -1e30f;
        float m = fmaxf(fmaxf(v0, v1), v2);
        for (int o = 16; o; o >>= 1) m = fmaxf(m, __shfl_xor_sync(~0u, m, o));
        float e0 = __expf(v0 - m), e1 = __expf(v1 - m);
        float e2 = (lane < 16) ? __expf(v2 - m) : 0.f;
        float s = e0 + e1 + e2;
        for (int o = 16; o; o >>= 1) s += __shfl_xor_sync(~0u, s, o);
        float inv = 1.f / s;
        sc[warp][lane]      = e0 * inv;
        sc[warp][lane + 32] = e1 * inv;
        if (lane < 16) sc[warp][lane + 64] = e2 * inv;
    }
    __syncthreads();

    for (int e = tid; e < 8*32; e += 256) {
        int qi = e >> 5, d2 = e & 31;
        float ax = 0.f, ay = 0.f;
#pragma unroll
        for (int kk = 0; kk < 80; kk++) {
            float s = sc[qi][kk];
            __half2 vh = *(const __half2*)&vsw[kk][d2 ^ (kk & 31)];
            float2 v = __half22float2(vh);
            ax += s * v.x; ay += s * v.y;
        }
        *(__half2*)&out[((size_t)b*SPD + n*ABB + qi) * DD + h*DHH + d2*2] =
            __floats2half2_rn(ax, ay);
    }
}

// ---------------- fused residual add (half) + LayerNorm (fp32+fp16 out) ------
__global__ void add_ln(float* __restrict__ h, __half* __restrict__ hh,
                       const __half* __restrict__ a,
                       const float* __restrict__ g, const float* __restrict__ be)
{
    int row = blockIdx.x;
    int tid = threadIdx.x;          // 256
    float* hr = h + (size_t)row * DD;
    __half* hhr = hh + (size_t)row * DD;
    const __half* ar = a + (size_t)row * DD;
    float x0 = hr[tid]       + __half2float(ar[tid]);
    float x1 = hr[tid + 256] + __half2float(ar[tid + 256]);
    float s = x0 + x1, q = x0*x0 + x1*x1;
    for (int o = 16; o; o >>= 1) {
        s += __shfl_xor_sync(~0u, s, o);
        q += __shfl_xor_sync(~0u, q, o);
    }
    __shared__ float ss[8], sq[8];
    int w = tid >> 5, l = tid & 31;
    if (l == 0) { ss[w] = s; sq[w] = q; }
    __syncthreads();
    if (tid == 0) {
        float S = 0, Q = 0;
        for (int i = 0; i < 8; i++) { S += ss[i]; Q += sq[i]; }
        ss[0] = S * (1.f/512.f);
        sq[0] = Q * (1.f/512.f);
    }
    __syncthreads();
    float m = ss[0];
    float inv = rsqrtf(sq[0] - m*m + 1e-5f);
    float y0 = (x0 - m) * inv * g[tid]       + be[tid];
    float y1 = (x1 - m) * inv * g[tid + 256] + be[tid + 256];
    hr[tid]        = y0;
    hr[tid + 256]  = y1;
    hhr[tid]       = __float2half_rn(y0);
    hhr[tid + 256] = __float2half_rn(y1);
}

// ---------------- latent head ----------
__global__ void latent(const float* __restrict__ Wm, const float* __restrict__ bm,
                       const float* __restrict__ Wl, const float* __restrict__ bl,
                       const float* __restrict__ eps)
{
    int b = blockIdx.x, t = threadIdx.x;   // 16 threads
    const float* p = g_h + (size_t)b * SPD * DD;
    float m = bm[t], l = bl[t];
    for (int d = 0; d < DD; d++) {
        float pv = p[d];
        m += pv * Wm[d*LATD + t];
        l += pv * Wl[d*LATD + t];
    }
    g_z[b*LATD + t] = m + eps[b*LATD + t] * __expf(0.5f * l);
    float c = 1.f + l - m*m - __expf(l);
    for (int o = 8; o; o >>= 1) c += __shfl_xor_sync(0xffffu, c, o, 16);
    if (t == 0) g_elbo_b[b] = -0.5f * c;
}

__global__ void seq_expand(const float* __restrict__ We, const float* __restrict__ be)
{
    int idx = blockIdx.x * 256 + threadIdx.x;
    if (idx >= BB * 2 * MSEQ) return;
    int b = idx >> 11, o = idx & 2047;
    float s = be[o];
#pragma unroll
    for (int j = 0; j < 16; j++) s += g_z[b*16 + j] * We[j*2048 + o];
    g_seq[idx] = s;
}

__global__ void dec_init(const float* __restrict__ Wc, const float* __restrict__ bc,
                         const float* __restrict__ embo)
{
    int idx = blockIdx.x * 256 + threadIdx.x;
    if (idx >= BB * MSEQ * DD) return;
    int d = idx & 511;
    int s = (idx >> 9) & 1023;
    int b = idx >> 19;
    float v = g_seq[b*2048 + s]        * Wc[d]
            + g_seq[b*2048 + 1024 + s] * Wc[512 + d]
            + bc[d] + embo[s*DD + d];
    size_t o = ((size_t)b*SPD + s) * DD + d;
    g_h[o] = v;
    g_hh[o] = __float2half_rn(v);
}

__global__ void zero_pad_rows()
{
    int idx = blockIdx.x * 256 + threadIdx.x;
    int nper = (SPD - MSEQ) * DD;
    if (idx >= BB * nper) return;
    int b = idx / nper;
    int r = idx % nper;
    size_t o = ((size_t)b*SPD + MSEQ) * DD + r;
    g_h[o] = 0.f;
    g_hh[o] = __float2half_rn(0.f);
}

__global__ void out_proj(const float* __restrict__ Ws, const float* __restrict__ bs,
                         float* __restrict__ out)
{
    int idx = blockIdx.x * 256 + threadIdx.x;
    if (idx >= BB * MSEQ * 16) return;
    int j = idx & 15;
    int s = (idx >> 4) & 1023;
    int b = idx >> 14;
    const float* hr = g_h + ((size_t)b*SPD + s) * DD;
    float acc = bs[j];
    for (int d = 0; d < DD; d++) acc += hr[d] * Ws[d*16 + j];
    out[idx] = acc;
}

__global__ void elbo_fin(float* out, int out_size)
{
    if (threadIdx.x == 0 && out_size > BB*MSEQ*16) {
        float s = 0.f;
        for (int i = 0; i < BB; i++) s += g_elbo_b[i];
        out[BB*MSEQ*16] = s * (1.f / BB);
    }
}

// ---------------- launch ----------------
extern "C" void kernel_launch(void* const* d_in, const int* in_sizes, int n_in,
                              void* d_out, int out_size)
{
    const float* x       = (const float*)d_in[0];
    const float* eps     = (const float*)d_in[1];
    const float* emb_in  = (const float*)d_in[2];
    const float* emb_out = (const float*)d_in[3];
    const float* W_data  = (const float*)d_in[4];
    const float* b_data  = (const float*)d_in[5];
    const float* Wqkv    = (const float*)d_in[6];
    const float* bqkv    = (const float*)d_in[7];
    const float* Wo      = (const float*)d_in[8];
    const float* bo      = (const float*)d_in[9];
    const float* ln1_g   = (const float*)d_in[10];
    const float* ln1_b   = (const float*)d_in[11];
    const float* W1      = (const float*)d_in[12];
    const float* b1      = (const float*)d_in[13];
    const float* W2      = (const float*)d_in[14];
    const float* b2      = (const float*)d_in[15];
    const float* ln2_g   = (const float*)d_in[16];
    const float* ln2_b   = (const float*)d_in[17];
    const float* W_mean  = (const float*)d_in[18];
    const float* b_mean  = (const float*)d_in[19];
    const float* W_lv    = (const float*)d_in[20];
    const float* b_lv    = (const float*)d_in[21];
    const float* W_exp   = (const float*)d_in[22];
    const float* b_exp   = (const float*)d_in[23];
    const float* W_conv  = (const float*)d_in[24];
    const float* b_conv  = (const float*)d_in[25];
    const float* W_seq   = (const float*)d_in[26];
    const float* b_seq   = (const float*)d_in[27];
    const int*   rand_enc= (const int*)d_in[28];
    const int*   rand_dec= (const int*)d_in[29];

    float *h_;
    __half *hh_, *qkvh_, *atth_, *tmph_, *ffh_, *wb_;
    cudaGetSymbolAddress((void**)&h_,    g_h);
    cudaGetSymbolAddress((void**)&hh_,   g_hh);
    cudaGetSymbolAddress((void**)&qkvh_, g_qkvh);
    cudaGetSymbolAddress((void**)&atth_, g_atth);
    cudaGetSymbolAddress((void**)&tmph_, g_tmph);
    cudaGetSymbolAddress((void**)&ffh_,  g_ffh);
    cudaGetSymbolAddress((void**)&wb_,   g_wb);

    cudaFuncSetAttribute(gemm_tc, cudaFuncAttributeMaxDynamicSharedMemorySize, SMEM_GEMM);

    const int M = MTOT;

    wconv<<<dim3(1536/32, 512/32, 10), dim3(32,8)>>>(Wqkv, wb_,
        512, 1536, (size_t)512*1536, WB_PER_LAYER);
    wconv<<<dim3(512/32, 512/32, 10), dim3(32,8)>>>(Wo, wb_ + 786432,
        512, 512, (size_t)512*512, WB_PER_LAYER);
    wconv<<<dim3(2048/32, 512/32, 10), dim3(32,8)>>>(W1, wb_ + 1048576,
        512, 2048, (size_t)512*2048, WB_PER_LAYER);
    wconv<<<dim3(512/32, 2048/32, 10), dim3(32,8)>>>(W2, wb_ + 2097152,
        2048, 512, (size_t)2048*512, WB_PER_LAYER);

    embed_enc<<<(BB*SPD*DD + 255)/256, 256>>>(x, W_data, b_data, emb_in);

    for (int i = 0; i < 10; i++) {
        const int* rnd = (i < 5) ? rand_enc : rand_dec;
        int nb = (i < 5) ? 129 : 128;
        int S  = (i < 5) ? 1025 : 1024;
        size_t L = (size_t)i * WB_PER_LAYER;

        gemm_tc<<<dim3(12, M/128), 256, SMEM_GEMM>>>(hh_, wb_ + L,
            bqkv + (size_t)i*1536, qkvh_, 1536, 512, 2);
        attn_kernel<<<dim3(nb, HH, BB), 256>>>(qkvh_, atth_, rnd, nb, S);
        gemm_tc<<<dim3(4, M/128), 256, SMEM_GEMM>>>(atth_, wb_ + L + 786432,
            bo + (size_t)i*512, tmph_, 512, 512, 2);
        add_ln<<<M, 256>>>(h_, hh_, tmph_, ln1_g + (size_t)i*DD, ln1_b + (size_t)i*DD);
        gemm_tc<<<dim3(16, M/128), 256, SMEM_GEMM>>>(hh_, wb_ + L + 1048576,
            b1 + (size_t)i*FFD, ffh_, 2048, 512, 1);
        gemm_tc<<<dim3(4, M/128), 256, SMEM_GEMM>>>(ffh_, wb_ + L + 2097152,
            b2 + (size_t)i*512, tmph_, 512, 2048, 2);
        add_ln<<<M, 256>>>(h_, hh_, tmph_, ln2_g + (size_t)i*DD, ln2_b + (size_t)i*DD);

        if (i == 4) {
            latent<<<BB, 16>>>(W_mean, b_mean, W_lv, b_lv, eps);
            seq_expand<<<(BB*2*MSEQ + 255)/256, 256>>>(W_exp, b_exp);
            dec_init<<<(BB*MSEQ*DD + 255)/256, 256>>>(W_conv, b_conv, emb_out);
            zero_pad_rows<<<(BB*(SPD-MSEQ)*DD + 255)/256, 256>>>();
        }
    }

    out_proj<<<(BB*MSEQ*16 + 255)/256, 256>>>(W_seq, b_seq, (float*)d_out);
    elbo_fin<<<1, 32>>>((float*)d_out, out_size);
}

// round 13
// speedup vs baseline: 1.0589x; 1.0589x over previous
#include <cuda_runtime.h>
#include <cuda_bf16.h>
#include <cuda_fp16.h>
#include <cstdint>
#include <cstdio>

// ---------------- constants ----------------
#define BB   32
#define DD   512
#define HH   8
#define DHH  64
#define ABB  8
#define KK   10
#define SPD  1032
#define FFD  2048
#define LATD 16
#define MSEQ 1024
#define MTOT (BB*SPD)          // 33024 = 258*128

#define WB_PER_LAYER 3145728   // qkv 786432 + wo 262144 + w1 1048576 + w2 1048576

// ---------------- scratch (device globals; no allocation) ----------------
__device__ float  g_h   [(size_t)BB*SPD*DD];
__device__ __align__(16) __half g_hh  [(size_t)BB*SPD*DD];
__device__ __align__(16) __half g_qkvh[(size_t)BB*SPD*3*DD];
__device__ __align__(16) __half g_atth[(size_t)BB*SPD*DD];
__device__ __align__(16) __half g_tmph[(size_t)BB*SPD*DD];
__device__ __align__(16) __half g_ffh [(size_t)BB*SPD*FFD];
__device__ float  g_z   [BB*LATD];
__device__ float  g_seq [BB*2*MSEQ];
__device__ float  g_elbo_b[BB];
__device__ __align__(16) __half g_wb[(size_t)10*WB_PER_LAYER];

// ---------------- helpers ----------------
#define CPA(smaddr, gptr) \
    asm volatile("cp.async.cg.shared.global [%0], [%1], 16;" :: "r"(smaddr), "l"(gptr))
#define CPC()  asm volatile("cp.async.commit_group;" ::: "memory")
#define CPW1() asm volatile("cp.async.wait_group 1;" ::: "memory")

__device__ __forceinline__ void ldsm4(uint32_t* r, uint32_t addr)
{
    asm volatile("ldmatrix.sync.aligned.m8n8.x4.shared.b16 {%0,%1,%2,%3}, [%4];"
        : "=r"(r[0]), "=r"(r[1]), "=r"(r[2]), "=r"(r[3]) : "r"(addr));
}
__device__ __forceinline__ void mma_f16(float* d, const uint32_t* a, const uint32_t* b)
{
    asm volatile("mma.sync.aligned.m16n8k16.row.col.f32.f16.f16.f32 "
        "{%0,%1,%2,%3}, {%4,%5,%6,%7}, {%8,%9}, {%0,%1,%2,%3};"
        : "+f"(d[0]), "+f"(d[1]), "+f"(d[2]), "+f"(d[3])
        : "r"(a[0]), "r"(a[1]), "r"(a[2]), "r"(a[3]), "r"(b[0]), "r"(b[1]));
}

// smem geometry for gemm: XOR-swizzled 128B rows, 3-stage pipeline
#define TILEB  (128*128)            // 16384: 128 rows x 64 halves
#define BUFB   (2*TILEB)            // 32768: A, W
#define SM_BUF 1024
#define SMEM_GEMM (SM_BUF + 3*BUFB) // 99328

// ---------------- weight transpose to fp16: W[K,N] -> Wh[N,K], batched -------
__global__ void wconv(const float* __restrict__ W, __half* __restrict__ hi,
                      int K, int N, size_t win_str, size_t wout_str)
{
    __shared__ float t[32][33];
    const float* Wl = W + (size_t)blockIdx.z * win_str;
    __half* hl = hi + (size_t)blockIdx.z * wout_str;
    int k0 = blockIdx.y * 32, n0 = blockIdx.x * 32;
    int tx = threadIdx.x, ty = threadIdx.y;   // 32 x 8
#pragma unroll
    for (int i = 0; i < 32; i += 8)
        t[ty + i][tx] = Wl[(size_t)(k0 + ty + i) * N + n0 + tx];
    __syncthreads();
#pragma unroll
    for (int i = 0; i < 32; i += 8)
        hl[(size_t)(n0 + ty + i) * K + k0 + tx] = __float2half_rn(t[tx][ty + i]);
}

// ---------------- tensor-core GEMM (mma.sync fp16, swizzled, 3-stage) ---------
// C[M,N] = A @ W^T + bias.  A fp16 [M,Kd]; W fp16 [N,Kd].
// mode 1: fp16 out + relu.  mode 2: fp16 out.
__global__ void __launch_bounds__(256) gemm_tc(
    const __half* __restrict__ A, const __half* __restrict__ W,
    const float* __restrict__ bias, __half* __restrict__ C,
    int N, int Kd, int mode)
{
    extern __shared__ char smem[];
    const int tid = threadIdx.x;
    const int lane = tid & 31, wid = tid >> 5;
    const int wr = wid >> 2, wc = wid & 3;          // 2 x 4 warp grid
    const int m0 = blockIdx.y * 128, n0 = blockIdx.x * 128;

    uint32_t sb;
    asm("{ .reg .u64 t; cvta.to.shared.u64 t, %1; cvt.u32.u64 %0, t; }"
        : "=r"(sb) : "l"(smem));

    float* biasS = (float*)smem;
    if (tid < 128) biasS[tid] = bias[n0 + tid];

    const int CHK = Kd >> 6;

    // swizzled cp.async loader: row r (128B), nominal seg s -> seg s^(r&7)
#define LOAD_TILE(dstoff, gbase)                                                 \
    {                                                                            \
        _Pragma("unroll")                                                        \
        for (int it = 0; it < 4; it++) {                                         \
            int s = it*256 + tid;                                                \
            int r = s >> 3, seg = s & 7;                                         \
            const __half* gp = (gbase) + (size_t)r * Kd + seg*8;                 \
            CPA(sb + (dstoff) + r*128 + ((seg ^ (r & 7)) << 4), gp);             \
        }                                                                        \
    }

#define LOAD_CHUNK(buf, c)                                                       \
    {                                                                            \
        const __half* ao = A + (size_t)m0*Kd + (c)*64;                           \
        const __half* wo = W + (size_t)n0*Kd + (c)*64;                           \
        LOAD_TILE(SM_BUF + (buf)*BUFB + 0*TILEB, ao);                            \
        LOAD_TILE(SM_BUF + (buf)*BUFB + 1*TILEB, wo);                            \
        CPC();                                                                   \
    }

    LOAD_CHUNK(0, 0);
    LOAD_CHUNK(1, 1);

    float acc[4][4][4] = {};

    uint32_t arow[4], akey[4];
#pragma unroll
    for (int i = 0; i < 4; i++) {
        uint32_t ra = wr*64 + i*16 + (lane & 15);
        arow[i] = ra * 128;
        akey[i] = ra & 7;
    }
    const uint32_t ahi = lane >> 4;
    uint32_t brow[2], bkey[2];
#pragma unroll
    for (int g = 0; g < 2; g++) {
        uint32_t rb = wc*32 + g*16 + (lane >> 4)*8 + (lane & 7);
        brow[g] = rb * 128;
        bkey[g] = rb & 7;
    }
    const uint32_t bhi = (lane >> 3) & 1;

    int cb = 0;
    for (int c = 0; c < CHK; c++) {
        CPW1();
        __syncthreads();
        if (c + 2 < CHK) {
            int nb3 = cb + 2; if (nb3 >= 3) nb3 -= 3;
            LOAD_CHUNK(nb3, c + 2);
        } else {
            CPC();
        }
        uint32_t Bs = sb + SM_BUF + cb*BUFB;
#pragma unroll
        for (int ks = 0; ks < 4; ks++) {
            uint32_t ca = ks*2 + ahi;
            uint32_t cbn = ks*2 + bhi;
            uint32_t ar[4][4], br[2][4];
#pragma unroll
            for (int i = 0; i < 4; i++)
                ldsm4(ar[i], Bs + arow[i] + (((ca ^ akey[i])) << 4));
#pragma unroll
            for (int g = 0; g < 2; g++)
                ldsm4(br[g], Bs + TILEB + brow[g] + (((cbn ^ bkey[g])) << 4));
#pragma unroll
            for (int i = 0; i < 4; i++)
#pragma unroll
            for (int j = 0; j < 4; j++)
                mma_f16(acc[i][j], ar[i], &br[j >> 1][(j & 1)*2]);
        }
        cb = (cb + 1 == 3) ? 0 : cb + 1;
    }

    // epilogue (fp16 out)
#pragma unroll
    for (int i = 0; i < 4; i++) {
        int row = m0 + wr*64 + i*16 + (lane >> 2);
#pragma unroll
        for (int j = 0; j < 4; j++) {
            int col = n0 + wc*32 + j*8 + (lane & 3)*2;
            float b0 = biasS[col - n0], b1 = biasS[col - n0 + 1];
            float v00 = acc[i][j][0] + b0, v01 = acc[i][j][1] + b1;
            float v10 = acc[i][j][2] + b0, v11 = acc[i][j][3] + b1;
            if (mode == 1) {
                v00 = fmaxf(v00, 0.f); v01 = fmaxf(v01, 0.f);
                v10 = fmaxf(v10, 0.f); v11 = fmaxf(v11, 0.f);
            }
            *(__half2*)&C[(size_t)row * N + col]       = __floats2half2_rn(v00, v01);
            *(__half2*)&C[(size_t)(row + 8) * N + col] = __floats2half2_rn(v10, v11);
        }
    }
#undef LOAD_TILE
#undef LOAD_CHUNK
}

// ---------------- encoder embedding (writes h fp32 + fp16) ----------------
__global__ void embed_enc(const float* __restrict__ x, const float* __restrict__ Wd,
                          const float* __restrict__ bd, const float* __restrict__ emb)
{
    int idx = blockIdx.x * blockDim.x + threadIdx.x;
    if (idx >= BB*SPD*DD) return;
    int d = idx & 511;
    int s = (idx >> 9) % SPD;
    int b = idx / (SPD*DD);
    float v = 0.f;
    if (s < MSEQ + 1) {
        v = emb[s*DD + d];
        if (s > 0) {
            const float* xr = x + ((size_t)b*MSEQ + (s-1)) * 16;
            float acc = bd[d];
#pragma unroll
            for (int j = 0; j < 16; j++) acc += xr[j] * Wd[j*DD + d];
            v += acc;
        }
    }
    g_h[idx] = v;
    g_hh[idx] = __float2half_rn(v);
}

// ---------------- block-sparse attention (fp16 in/out, fp32 accumulate) -------
// K/V smem rows have stride 33 words (odd => conflict-free column access in the
// score loop; row access in AV loop trivially conflict-free). Stores are 4B.
__global__ void attn_kernel(const __half* __restrict__ qkv, __half* __restrict__ out,
                            const int* __restrict__ rnd, int nb, int S)
{
    int n = blockIdx.x, h = blockIdx.y, b = blockIdx.z;
    int tid = threadIdx.x;

    __shared__ __half2 qs[8][34];
    __shared__ __half2 ks[80][33];
    __shared__ __half2 vs[80][33];
    __shared__ float sc[8][80];
    __shared__ int   sbidx[KK];
    __shared__ int   svalid[KK];
    __shared__ float kmaskadd[80];

    if (tid < KK) {
        int j = tid, idx, valid = 1;
        if (j < 2)       { idx = j; }
        else if (j < 7)  { int w = n + j - 4; valid = (w >= 0 && w < nb);
                           idx = min(max(w, 0), nb - 1); }
        else             { idx = rnd[n*3 + (j - 7)]; }
        sbidx[j]  = idx;
        svalid[j] = valid;
    }
    __syncthreads();
    if (tid < 80) {
        int j = tid >> 3, p = tid & 7;
        int tok = sbidx[j]*ABB + p;
        kmaskadd[tid] = (svalid[j] && tok < S) ? 0.f : -1e9f;
    }

    const __half* base = qkv + (size_t)b * SPD * (3*DD);
    if (tid < 128) {
        int p = tid >> 4, seg = tid & 15;
        uint2 v = *(const uint2*)(base + (size_t)(n*ABB + p)*(3*DD) + h*DHH + seg*4);
        *(uint2*)&qs[p][seg*2] = v;
    }
    // K/V gather: 8B global loads, two 4B smem stores each (odd row stride)
    for (int e = tid; e < 80*16; e += 256) {
        int kk = e >> 4, seg = e & 15;
        int j = kk >> 3, p = kk & 7;
        int row = sbidx[j]*ABB + p;
        const __half* rp = base + (size_t)row*(3*DD) + h*DHH + seg*4;
        uint2 kv = *(const uint2*)(rp + DD);
        uint2 vv = *(const uint2*)(rp + 2*DD);
        ks[kk][seg*2]     = *(__half2*)&kv.x;
        ks[kk][seg*2 + 1] = *(__half2*)&kv.y;
        vs[kk][seg*2]     = *(__half2*)&vv.x;
        vs[kk][seg*2 + 1] = *(__half2*)&vv.y;
    }
    __syncthreads();

    for (int e = tid; e < 640; e += 256) {
        int qi = e / 80, kk = e % 80;
        float s = 0.f;
#pragma unroll
        for (int d2 = 0; d2 < 32; d2++) {
            float2 a = __half22float2(qs[qi][d2]);
            float2 bb = __half22float2(ks[kk][d2]);
            s += a.x*bb.x + a.y*bb.y;
        }
        sc[qi][kk] = s * 0.125f + kmaskadd[kk];
    }
    __syncthreads();

    int warp = tid >> 5, lane = tid & 31;
    if (warp < 8) {
        float v0 = sc[warp][lane];
        float v1 = sc[warp][lane + 32];
        float v2 = (lane < 16) ? sc[warp][lane + 64] : -1e30f;
        float m = fmaxf(fmaxf(v0, v1), v2);
        for (int o = 16; o; o >>= 1) m = fmaxf(m, __shfl_xor_sync(~0u, m, o));
        float e0 = __expf(v0 - m), e1 = __expf(v1 - m);
        float e2 = (lane < 16) ? __expf(v2 - m) : 0.f;
        float s = e0 + e1 + e2;
        for (int o = 16; o; o >>= 1) s += __shfl_xor_sync(~0u, s, o);
        float inv = 1.f / s;
        sc[warp][lane]      = e0 * inv;
        sc[warp][lane + 32] = e1 * inv;
        if (lane < 16) sc[warp][lane + 64] = e2 * inv;
    }
    __syncthreads();

    for (int e = tid; e < 8*32; e += 256) {
        int qi = e >> 5, d2 = e & 31;
        float ax = 0.f, ay = 0.f;
#pragma unroll
        for (int kk = 0; kk < 80; kk++) {
            float s = sc[qi][kk];
            float2 v = __half22float2(vs[kk][d2]);
            ax += s * v.x; ay += s * v.y;
        }
        *(__half2*)&out[((size_t)b*SPD + n*ABB + qi) * DD + h*DHH + d2*2] =
            __floats2half2_rn(ax, ay);
    }
}

// ---------------- fused residual add (half) + LayerNorm (fp32+fp16 out) ------
__global__ void add_ln(float* __restrict__ h, __half* __restrict__ hh,
                       const __half* __restrict__ a,
                       const float* __restrict__ g, const float* __restrict__ be)
{
    int row = blockIdx.x;
    int tid = threadIdx.x;          // 256
    float* hr = h + (size_t)row * DD;
    __half* hhr = hh + (size_t)row * DD;
    const __half* ar = a + (size_t)row * DD;
    float x0 = hr[tid]       + __half2float(ar[tid]);
    float x1 = hr[tid + 256] + __half2float(ar[tid + 256]);
    float s = x0 + x1, q = x0*x0 + x1*x1;
    for (int o = 16; o; o >>= 1) {
        s += __shfl_xor_sync(~0u, s, o);
        q += __shfl_xor_sync(~0u, q, o);
    }
    __shared__ float ss[8], sq[8];
    int w = tid >> 5, l = tid & 31;
    if (l == 0) { ss[w] = s; sq[w] = q; }
    __syncthreads();
    if (tid == 0) {
        float S = 0, Q = 0;
        for (int i = 0; i < 8; i++) { S += ss[i]; Q += sq[i]; }
        ss[0] = S * (1.f/512.f);
        sq[0] = Q * (1.f/512.f);
    }
    __syncthreads();
    float m = ss[0];
    float inv = rsqrtf(sq[0] - m*m + 1e-5f);
    float y0 = (x0 - m) * inv * g[tid]       + be[tid];
    float y1 = (x1 - m) * inv * g[tid + 256] + be[tid + 256];
    hr[tid]        = y0;
    hr[tid + 256]  = y1;
    hhr[tid]       = __float2half_rn(y0);
    hhr[tid + 256] = __float2half_rn(y1);
}

// ---------------- latent head ----------
__global__ void latent(const float* __restrict__ Wm, const float* __restrict__ bm,
                       const float* __restrict__ Wl, const float* __restrict__ bl,
                       const float* __restrict__ eps)
{
    int b = blockIdx.x, t = threadIdx.x;   // 16 threads
    const float* p = g_h + (size_t)b * SPD * DD;
    float m = bm[t], l = bl[t];
    for (int d = 0; d < DD; d++) {
        float pv = p[d];
        m += pv * Wm[d*LATD + t];
        l += pv * Wl[d*LATD + t];
    }
    g_z[b*LATD + t] = m + eps[b*LATD + t] * __expf(0.5f * l);
    float c = 1.f + l - m*m - __expf(l);
    for (int o = 8; o; o >>= 1) c += __shfl_xor_sync(0xffffu, c, o, 16);
    if (t == 0) g_elbo_b[b] = -0.5f * c;
}

__global__ void seq_expand(const float* __restrict__ We, const float* __restrict__ be)
{
    int idx = blockIdx.x * 256 + threadIdx.x;
    if (idx >= BB * 2 * MSEQ) return;
    int b = idx >> 11, o = idx & 2047;
    float s = be[o];
#pragma unroll
    for (int j = 0; j < 16; j++) s += g_z[b*16 + j] * We[j*2048 + o];
    g_seq[idx] = s;
}

__global__ void dec_init(const float* __restrict__ Wc, const float* __restrict__ bc,
                         const float* __restrict__ embo)
{
    int idx = blockIdx.x * 256 + threadIdx.x;
    if (idx >= BB * MSEQ * DD) return;
    int d = idx & 511;
    int s = (idx >> 9) & 1023;
    int b = idx >> 19;
    float v = g_seq[b*2048 + s]        * Wc[d]
            + g_seq[b*2048 + 1024 + s] * Wc[512 + d]
            + bc[d] + embo[s*DD + d];
    size_t o = ((size_t)b*SPD + s) * DD + d;
    g_h[o] = v;
    g_hh[o] = __float2half_rn(v);
}

__global__ void zero_pad_rows()
{
    int idx = blockIdx.x * 256 + threadIdx.x;
    int nper = (SPD - MSEQ) * DD;
    if (idx >= BB * nper) return;
    int b = idx / nper;
    int r = idx % nper;
    size_t o = ((size_t)b*SPD + MSEQ) * DD + r;
    g_h[o] = 0.f;
    g_hh[o] = __float2half_rn(0.f);
}

__global__ void out_proj(const float* __restrict__ Ws, const float* __restrict__ bs,
                         float* __restrict__ out)
{
    int idx = blockIdx.x * 256 + threadIdx.x;
    if (idx >= BB * MSEQ * 16) return;
    int j = idx & 15;
    int s = (idx >> 4) & 1023;
    int b = idx >> 14;
    const float* hr = g_h + ((size_t)b*SPD + s) * DD;
    float acc = bs[j];
    for (int d = 0; d < DD; d++) acc += hr[d] * Ws[d*16 + j];
    out[idx] = acc;
}

__global__ void elbo_fin(float* out, int out_size)
{
    if (threadIdx.x == 0 && out_size > BB*MSEQ*16) {
        float s = 0.f;
        for (int i = 0; i < BB; i++) s += g_elbo_b[i];
        out[BB*MSEQ*16] = s * (1.f / BB);
    }
}

// ---------------- launch ----------------
extern "C" void kernel_launch(void* const* d_in, const int* in_sizes, int n_in,
                              void* d_out, int out_size)
{
    const float* x       = (const float*)d_in[0];
    const float* eps     = (const float*)d_in[1];
    const float* emb_in  = (const float*)d_in[2];
    const float* emb_out = (const float*)d_in[3];
    const float* W_data  = (const float*)d_in[4];
    const float* b_data  = (const float*)d_in[5];
    const float* Wqkv    = (const float*)d_in[6];
    const float* bqkv    = (const float*)d_in[7];
    const float* Wo      = (const float*)d_in[8];
    const float* bo      = (const float*)d_in[9];
    const float* ln1_g   = (const float*)d_in[10];
    const float* ln1_b   = (const float*)d_in[11];
    const float* W1      = (const float*)d_in[12];
    const float* b1      = (const float*)d_in[13];
    const float* W2      = (const float*)d_in[14];
    const float* b2      = (const float*)d_in[15];
    const float* ln2_g   = (const float*)d_in[16];
    const float* ln2_b   = (const float*)d_in[17];
    const float* W_mean  = (const float*)d_in[18];
    const float* b_mean  = (const float*)d_in[19];
    const float* W_lv    = (const float*)d_in[20];
    const float* b_lv    = (const float*)d_in[21];
    const float* W_exp   = (const float*)d_in[22];
    const float* b_exp   = (const float*)d_in[23];
    const float* W_conv  = (const float*)d_in[24];
    const float* b_conv  = (const float*)d_in[25];
    const float* W_seq   = (const float*)d_in[26];
    const float* b_seq   = (const float*)d_in[27];
    const int*   rand_enc= (const int*)d_in[28];
    const int*   rand_dec= (const int*)d_in[29];

    float *h_;
    __half *hh_, *qkvh_, *atth_, *tmph_, *ffh_, *wb_;
    cudaGetSymbolAddress((void**)&h_,    g_h);
    cudaGetSymbolAddress((void**)&hh_,   g_hh);
    cudaGetSymbolAddress((void**)&qkvh_, g_qkvh);
    cudaGetSymbolAddress((void**)&atth_, g_atth);
    cudaGetSymbolAddress((void**)&tmph_, g_tmph);
    cudaGetSymbolAddress((void**)&ffh_,  g_ffh);
    cudaGetSymbolAddress((void**)&wb_,   g_wb);

    cudaFuncSetAttribute(gemm_tc, cudaFuncAttributeMaxDynamicSharedMemorySize, SMEM_GEMM);

    const int M = MTOT;

    wconv<<<dim3(1536/32, 512/32, 10), dim3(32,8)>>>(Wqkv, wb_,
        512, 1536, (size_t)512*1536, WB_PER_LAYER);
    wconv<<<dim3(512/32, 512/32, 10), dim3(32,8)>>>(Wo, wb_ + 786432,
        512, 512, (size_t)512*512, WB_PER_LAYER);
    wconv<<<dim3(2048/32, 512/32, 10), dim3(32,8)>>>(W1, wb_ + 1048576,
        512, 2048, (size_t)512*2048, WB_PER_LAYER);
    wconv<<<dim3(512/32, 2048/32, 10), dim3(32,8)>>>(W2, wb_ + 2097152,
        2048, 512, (size_t)2048*512, WB_PER_LAYER);

    embed_enc<<<(BB*SPD*DD + 255)/256, 256>>>(x, W_data, b_data, emb_in);

    for (int i = 0; i < 10; i++) {
        const int* rnd = (i < 5) ? rand_enc : rand_dec;
        int nb = (i < 5) ? 129 : 128;
        int S  = (i < 5) ? 1025 : 1024;
        size_t L = (size_t)i * WB_PER_LAYER;

        gemm_tc<<<dim3(12, M/128), 256, SMEM_GEMM>>>(hh_, wb_ + L,
            bqkv + (size_t)i*1536, qkvh_, 1536, 512, 2);
        attn_kernel<<<dim3(nb, HH, BB), 256>>>(qkvh_, atth_, rnd, nb, S);
        gemm_tc<<<dim3(4, M/128), 256, SMEM_GEMM>>>(atth_, wb_ + L + 786432,
            bo + (size_t)i*512, tmph_, 512, 512, 2);
        add_ln<<<M, 256>>>(h_, hh_, tmph_, ln1_g + (size_t)i*DD, ln1_b + (size_t)i*DD);
        gemm_tc<<<dim3(16, M/128), 256, SMEM_GEMM>>>(hh_, wb_ + L + 1048576,
            b1 + (size_t)i*FFD, ffh_, 2048, 512, 1);
        gemm_tc<<<dim3(4, M/128), 256, SMEM_GEMM>>>(ffh_, wb_ + L + 2097152,
            b2 + (size_t)i*512, tmph_, 512, 2048, 2);
        add_ln<<<M, 256>>>(h_, hh_, tmph_, ln2_g + (size_t)i*DD, ln2_b + (size_t)i*DD);

        if (i == 4) {
            latent<<<BB, 16>>>(W_mean, b_mean, W_lv, b_lv, eps);
            seq_expand<<<(BB*2*MSEQ + 255)/256, 256>>>(W_exp, b_exp);
            dec_init<<<(BB*MSEQ*DD + 255)/256, 256>>>(W_conv, b_conv, emb_out);
            zero_pad_rows<<<(BB*(SPD-MSEQ)*DD + 255)/256, 256>>>();
        }
    }

    out_proj<<<(BB*MSEQ*16 + 255)/256, 256>>>(W_seq, b_seq, (float*)d_out);
    elbo_fin<<<1, 32>>>((float*)d_out, out_size);
}

// round 14
// speedup vs baseline: 1.1095x; 1.0477x over previous
#include <cuda_runtime.h>
#include <cuda_bf16.h>
#include <cuda_fp16.h>
#include <cstdint>
#include <cstdio>

// ---------------- constants ----------------
#define BB   32
#define DD   512
#define HH   8
#define DHH  64
#define ABB  8
#define KK   10
#define SPD  1032
#define FFD  2048
#define LATD 16
#define MSEQ 1024
#define MTOT (BB*SPD)          // 33024 = 258*128

#define WB_PER_LAYER 3145728   // qkv 786432 + wo 262144 + w1 1048576 + w2 1048576

// ---------------- scratch (device globals; no allocation) ----------------
__device__ float  g_h   [(size_t)BB*SPD*DD];
__device__ __align__(16) __half g_hh  [(size_t)BB*SPD*DD];
__device__ __align__(16) __half g_qkvh[(size_t)BB*SPD*3*DD];
__device__ __align__(16) __half g_atth[(size_t)BB*SPD*DD];
__device__ __align__(16) __half g_tmph[(size_t)BB*SPD*DD];
__device__ __align__(16) __half g_ffh [(size_t)BB*SPD*FFD];
__device__ float  g_z   [BB*LATD];
__device__ float  g_seq [BB*2*MSEQ];
__device__ float  g_elbo_b[BB];
__device__ __align__(16) __half g_wb[(size_t)10*WB_PER_LAYER];

// ---------------- helpers ----------------
#define CPA(smaddr, gptr) \
    asm volatile("cp.async.cg.shared.global [%0], [%1], 16;" :: "r"(smaddr), "l"(gptr))
#define CPC()  asm volatile("cp.async.commit_group;" ::: "memory")
#define CPW1() asm volatile("cp.async.wait_group 1;" ::: "memory")

__device__ __forceinline__ void ldsm4(uint32_t* r, uint32_t addr)
{
    asm volatile("ldmatrix.sync.aligned.m8n8.x4.shared.b16 {%0,%1,%2,%3}, [%4];"
        : "=r"(r[0]), "=r"(r[1]), "=r"(r[2]), "=r"(r[3]) : "r"(addr));
}
__device__ __forceinline__ void mma_f16(float* d, const uint32_t* a, const uint32_t* b)
{
    asm volatile("mma.sync.aligned.m16n8k16.row.col.f32.f16.f16.f32 "
        "{%0,%1,%2,%3}, {%4,%5,%6,%7}, {%8,%9}, {%0,%1,%2,%3};"
        : "+f"(d[0]), "+f"(d[1]), "+f"(d[2]), "+f"(d[3])
        : "r"(a[0]), "r"(a[1]), "r"(a[2]), "r"(a[3]), "r"(b[0]), "r"(b[1]));
}

// smem geometry for gemm: XOR-swizzled 128B rows, 3-stage pipeline
#define TILEB  (128*128)            // 16384: 128 rows x 64 halves
#define BUFB   (2*TILEB)            // 32768: A, W
#define SM_BUF 1024
#define SMEM_GEMM (SM_BUF + 3*BUFB) // 99328

// ---------------- weight transpose to fp16: W[K,N] -> Wh[N,K], batched -------
__global__ void wconv(const float* __restrict__ W, __half* __restrict__ hi,
                      int K, int N, size_t win_str, size_t wout_str)
{
    __shared__ float t[32][33];
    const float* Wl = W + (size_t)blockIdx.z * win_str;
    __half* hl = hi + (size_t)blockIdx.z * wout_str;
    int k0 = blockIdx.y * 32, n0 = blockIdx.x * 32;
    int tx = threadIdx.x, ty = threadIdx.y;   // 32 x 8
#pragma unroll
    for (int i = 0; i < 32; i += 8)
        t[ty + i][tx] = Wl[(size_t)(k0 + ty + i) * N + n0 + tx];
    __syncthreads();
#pragma unroll
    for (int i = 0; i < 32; i += 8)
        hl[(size_t)(n0 + ty + i) * K + k0 + tx] = __float2half_rn(t[tx][ty + i]);
}

// ---------------- tensor-core GEMM (mma.sync fp16, swizzled, 3-stage) ---------
// C[M,N] = A @ W^T + bias.  A fp16 [M,Kd]; W fp16 [N,Kd].
// mode 1: fp16 out + relu.  mode 2: fp16 out.
__global__ void __launch_bounds__(256) gemm_tc(
    const __half* __restrict__ A, const __half* __restrict__ W,
    const float* __restrict__ bias, __half* __restrict__ C,
    int N, int Kd, int mode)
{
    extern __shared__ char smem[];
    const int tid = threadIdx.x;
    const int lane = tid & 31, wid = tid >> 5;
    const int wr = wid >> 2, wc = wid & 3;          // 2 x 4 warp grid
    const int m0 = blockIdx.y * 128, n0 = blockIdx.x * 128;

    uint32_t sb;
    asm("{ .reg .u64 t; cvta.to.shared.u64 t, %1; cvt.u32.u64 %0, t; }"
        : "=r"(sb) : "l"(smem));

    float* biasS = (float*)smem;
    if (tid < 128) biasS[tid] = bias[n0 + tid];

    const int CHK = Kd >> 6;

    // swizzled cp.async loader: row r (128B), nominal seg s -> seg s^(r&7)
#define LOAD_TILE(dstoff, gbase)                                                 \
    {                                                                            \
        _Pragma("unroll")                                                        \
        for (int it = 0; it < 4; it++) {                                         \
            int s = it*256 + tid;                                                \
            int r = s >> 3, seg = s & 7;                                         \
            const __half* gp = (gbase) + (size_t)r * Kd + seg*8;                 \
            CPA(sb + (dstoff) + r*128 + ((seg ^ (r & 7)) << 4), gp);             \
        }                                                                        \
    }

#define LOAD_CHUNK(buf, c)                                                       \
    {                                                                            \
        const __half* ao = A + (size_t)m0*Kd + (c)*64;                           \
        const __half* wo = W + (size_t)n0*Kd + (c)*64;                           \
        LOAD_TILE(SM_BUF + (buf)*BUFB + 0*TILEB, ao);                            \
        LOAD_TILE(SM_BUF + (buf)*BUFB + 1*TILEB, wo);                            \
        CPC();                                                                   \
    }

    LOAD_CHUNK(0, 0);
    LOAD_CHUNK(1, 1);

    float acc[4][4][4] = {};

    uint32_t arow[4], akey[4];
#pragma unroll
    for (int i = 0; i < 4; i++) {
        uint32_t ra = wr*64 + i*16 + (lane & 15);
        arow[i] = ra * 128;
        akey[i] = ra & 7;
    }
    const uint32_t ahi = lane >> 4;
    uint32_t brow[2], bkey[2];
#pragma unroll
    for (int g = 0; g < 2; g++) {
        uint32_t rb = wc*32 + g*16 + (lane >> 4)*8 + (lane & 7);
        brow[g] = rb * 128;
        bkey[g] = rb & 7;
    }
    const uint32_t bhi = (lane >> 3) & 1;

    int cb = 0;
    for (int c = 0; c < CHK; c++) {
        CPW1();
        __syncthreads();
        if (c + 2 < CHK) {
            int nb3 = cb + 2; if (nb3 >= 3) nb3 -= 3;
            LOAD_CHUNK(nb3, c + 2);
        } else {
            CPC();
        }
        uint32_t Bs = sb + SM_BUF + cb*BUFB;
#pragma unroll
        for (int ks = 0; ks < 4; ks++) {
            uint32_t ca = ks*2 + ahi;
            uint32_t cbn = ks*2 + bhi;
            uint32_t ar[4][4], br[2][4];
#pragma unroll
            for (int i = 0; i < 4; i++)
                ldsm4(ar[i], Bs + arow[i] + (((ca ^ akey[i])) << 4));
#pragma unroll
            for (int g = 0; g < 2; g++)
                ldsm4(br[g], Bs + TILEB + brow[g] + (((cbn ^ bkey[g])) << 4));
#pragma unroll
            for (int i = 0; i < 4; i++)
#pragma unroll
            for (int j = 0; j < 4; j++)
                mma_f16(acc[i][j], ar[i], &br[j >> 1][(j & 1)*2]);
        }
        cb = (cb + 1 == 3) ? 0 : cb + 1;
    }

    // epilogue (fp16 out)
#pragma unroll
    for (int i = 0; i < 4; i++) {
        int row = m0 + wr*64 + i*16 + (lane >> 2);
#pragma unroll
        for (int j = 0; j < 4; j++) {
            int col = n0 + wc*32 + j*8 + (lane & 3)*2;
            float b0 = biasS[col - n0], b1 = biasS[col - n0 + 1];
            float v00 = acc[i][j][0] + b0, v01 = acc[i][j][1] + b1;
            float v10 = acc[i][j][2] + b0, v11 = acc[i][j][3] + b1;
            if (mode == 1) {
                v00 = fmaxf(v00, 0.f); v01 = fmaxf(v01, 0.f);
                v10 = fmaxf(v10, 0.f); v11 = fmaxf(v11, 0.f);
            }
            *(__half2*)&C[(size_t)row * N + col]       = __floats2half2_rn(v00, v01);
            *(__half2*)&C[(size_t)(row + 8) * N + col] = __floats2half2_rn(v10, v11);
        }
    }
#undef LOAD_TILE
#undef LOAD_CHUNK
}

// ---------------- encoder embedding (writes h fp32 + fp16) ----------------
__global__ void embed_enc(const float* __restrict__ x, const float* __restrict__ Wd,
                          const float* __restrict__ bd, const float* __restrict__ emb)
{
    int idx = blockIdx.x * blockDim.x + threadIdx.x;
    if (idx >= BB*SPD*DD) return;
    int d = idx & 511;
    int s = (idx >> 9) % SPD;
    int b = idx / (SPD*DD);
    float v = 0.f;
    if (s < MSEQ + 1) {
        v = emb[s*DD + d];
        if (s > 0) {
            const float* xr = x + ((size_t)b*MSEQ + (s-1)) * 16;
            float acc = bd[d];
#pragma unroll
            for (int j = 0; j < 16; j++) acc += xr[j] * Wd[j*DD + d];
            v += acc;
        }
    }
    g_h[idx] = v;
    g_hh[idx] = __float2half_rn(v);
}

// ---------------- block-sparse attention (fp16 in/out, fp32 accumulate) -------
// R10 layout: rows padded to 34 half2 (136 B, 8B-aligned) for uint2 access.
__global__ void attn_kernel(const __half* __restrict__ qkv, __half* __restrict__ out,
                            const int* __restrict__ rnd, int nb, int S)
{
    int n = blockIdx.x, h = blockIdx.y, b = blockIdx.z;
    int tid = threadIdx.x;

    __shared__ __half2 qs[8][34];
    __shared__ __half2 ks[80][34];
    __shared__ __half2 vs[80][34];
    __shared__ float sc[8][80];
    __shared__ int   sbidx[KK];
    __shared__ int   svalid[KK];
    __shared__ float kmaskadd[80];

    if (tid < KK) {
        int j = tid, idx, valid = 1;
        if (j < 2)       { idx = j; }
        else if (j < 7)  { int w = n + j - 4; valid = (w >= 0 && w < nb);
                           idx = min(max(w, 0), nb - 1); }
        else             { idx = rnd[n*3 + (j - 7)]; }
        sbidx[j]  = idx;
        svalid[j] = valid;
    }
    __syncthreads();
    if (tid < 80) {
        int j = tid >> 3, p = tid & 7;
        int tok = sbidx[j]*ABB + p;
        kmaskadd[tid] = (svalid[j] && tok < S) ? 0.f : -1e9f;
    }

    const __half* base = qkv + (size_t)b * SPD * (3*DD);
    if (tid < 128) {
        int p = tid >> 4, seg = tid & 15;
        uint2 v = *(const uint2*)(base + (size_t)(n*ABB + p)*(3*DD) + h*DHH + seg*4);
        *(uint2*)&qs[p][seg*2] = v;
    }
    for (int e = tid; e < 80*16; e += 256) {
        int kk = e >> 4, seg = e & 15;
        int j = kk >> 3, p = kk & 7;
        int row = sbidx[j]*ABB + p;
        const __half* rp = base + (size_t)row*(3*DD) + h*DHH + seg*4;
        *(uint2*)&ks[kk][seg*2] = *(const uint2*)(rp + DD);
        *(uint2*)&vs[kk][seg*2] = *(const uint2*)(rp + 2*DD);
    }
    __syncthreads();

    for (int e = tid; e < 640; e += 256) {
        int qi = e / 80, kk = e % 80;
        float s = 0.f;
#pragma unroll
        for (int d2 = 0; d2 < 32; d2++) {
            float2 a = __half22float2(qs[qi][d2]);
            float2 bb = __half22float2(ks[kk][d2]);
            s += a.x*bb.x + a.y*bb.y;
        }
        sc[qi][kk] = s * 0.125f + kmaskadd[kk];
    }
    __syncthreads();

    int warp = tid >> 5, lane = tid & 31;
    if (warp < 8) {
        float v0 = sc[warp][lane];
        float v1 = sc[warp][lane + 32];
        float v2 = (lane < 16) ? sc[warp][lane + 64] : -1e30f;
        float m = fmaxf(fmaxf(v0, v1), v2);
        for (int o = 16; o; o >>= 1) m = fmaxf(m, __shfl_xor_sync(~0u, m, o));
        float e0 = __expf(v0 - m), e1 = __expf(v1 - m);
        float e2 = (lane < 16) ? __expf(v2 - m) : 0.f;
        float s = e0 + e1 + e2;
        for (int o = 16; o; o >>= 1) s += __shfl_xor_sync(~0u, s, o);
        float inv = 1.f / s;
        sc[warp][lane]      = e0 * inv;
        sc[warp][lane + 32] = e1 * inv;
        if (lane < 16) sc[warp][lane + 64] = e2 * inv;
    }
    __syncthreads();

    for (int e = tid; e < 8*32; e += 256) {
        int qi = e >> 5, d2 = e & 31;
        float ax = 0.f, ay = 0.f;
#pragma unroll
        for (int kk = 0; kk < 80; kk++) {
            float s = sc[qi][kk];
            float2 v = __half22float2(vs[kk][d2]);
            ax += s * v.x; ay += s * v.y;
        }
        *(__half2*)&out[((size_t)b*SPD + n*ABB + qi) * DD + h*DHH + d2*2] =
            __floats2half2_rn(ax, ay);
    }
}

// ---------------- fused residual add + LayerNorm: ONE WARP PER ROW ------------
// 8 rows per CTA, grid = MTOT/8. No __syncthreads, shfl-only reduction,
// float4/uint2 vectorized loads and stores.
__global__ void __launch_bounds__(256) add_ln(
    float* __restrict__ h, __half* __restrict__ hh,
    const __half* __restrict__ a,
    const float* __restrict__ g, const float* __restrict__ be)
{
    int warp = threadIdx.x >> 5, lane = threadIdx.x & 31;
    size_t row = (size_t)blockIdx.x * 8 + warp;
    float* hr = h + row * DD;
    __half* hhr = hh + row * DD;
    const uint2* ar = (const uint2*)(a + row * DD);

    float x[16];
    float s = 0.f, q = 0.f;
#pragma unroll
    for (int j = 0; j < 4; j++) {
        int f4 = lane + j*32;
        float4 hv = ((const float4*)hr)[f4];
        uint2 av = ar[f4];
        float2 f0 = __half22float2(*(__half2*)&av.x);
        float2 f1 = __half22float2(*(__half2*)&av.y);
        float x0 = hv.x + f0.x, x1 = hv.y + f0.y;
        float x2 = hv.z + f1.x, x3 = hv.w + f1.y;
        x[j*4+0] = x0; x[j*4+1] = x1; x[j*4+2] = x2; x[j*4+3] = x3;
        s += (x0 + x1) + (x2 + x3);
        q += (x0*x0 + x1*x1) + (x2*x2 + x3*x3);
    }
#pragma unroll
    for (int o = 16; o; o >>= 1) {
        s += __shfl_xor_sync(~0u, s, o);
        q += __shfl_xor_sync(~0u, q, o);
    }
    float m = s * (1.f/512.f);
    float inv = rsqrtf(q * (1.f/512.f) - m*m + 1e-5f);

#pragma unroll
    for (int j = 0; j < 4; j++) {
        int f4 = lane + j*32;
        float4 gv = ((const float4*)g)[f4];
        float4 bv = ((const float4*)be)[f4];
        float4 y;
        y.x = (x[j*4+0] - m) * inv * gv.x + bv.x;
        y.y = (x[j*4+1] - m) * inv * gv.y + bv.y;
        y.z = (x[j*4+2] - m) * inv * gv.z + bv.z;
        y.w = (x[j*4+3] - m) * inv * gv.w + bv.w;
        ((float4*)hr)[f4] = y;
        uint2 hv;
        *(__half2*)&hv.x = __floats2half2_rn(y.x, y.y);
        *(__half2*)&hv.y = __floats2half2_rn(y.z, y.w);
        ((uint2*)hhr)[f4] = hv;
    }
}

// ---------------- latent head ----------
__global__ void latent(const float* __restrict__ Wm, const float* __restrict__ bm,
                       const float* __restrict__ Wl, const float* __restrict__ bl,
                       const float* __restrict__ eps)
{
    int b = blockIdx.x, t = threadIdx.x;   // 16 threads
    const float* p = g_h + (size_t)b * SPD * DD;
    float m = bm[t], l = bl[t];
    for (int d = 0; d < DD; d++) {
        float pv = p[d];
        m += pv * Wm[d*LATD + t];
        l += pv * Wl[d*LATD + t];
    }
    g_z[b*LATD + t] = m + eps[b*LATD + t] * __expf(0.5f * l);
    float c = 1.f + l - m*m - __expf(l);
    for (int o = 8; o; o >>= 1) c += __shfl_xor_sync(0xffffu, c, o, 16);
    if (t == 0) g_elbo_b[b] = -0.5f * c;
}

__global__ void seq_expand(const float* __restrict__ We, const float* __restrict__ be)
{
    int idx = blockIdx.x * 256 + threadIdx.x;
    if (idx >= BB * 2 * MSEQ) return;
    int b = idx >> 11, o = idx & 2047;
    float s = be[o];
#pragma unroll
    for (int j = 0; j < 16; j++) s += g_z[b*16 + j] * We[j*2048 + o];
    g_seq[idx] = s;
}

__global__ void dec_init(const float* __restrict__ Wc, const float* __restrict__ bc,
                         const float* __restrict__ embo)
{
    int idx = blockIdx.x * 256 + threadIdx.x;
    if (idx >= BB * MSEQ * DD) return;
    int d = idx & 511;
    int s = (idx >> 9) & 1023;
    int b = idx >> 19;
    float v = g_seq[b*2048 + s]        * Wc[d]
            + g_seq[b*2048 + 1024 + s] * Wc[512 + d]
            + bc[d] + embo[s*DD + d];
    size_t o = ((size_t)b*SPD + s) * DD + d;
    g_h[o] = v;
    g_hh[o] = __float2half_rn(v);
}

__global__ void zero_pad_rows()
{
    int idx = blockIdx.x * 256 + threadIdx.x;
    int nper = (SPD - MSEQ) * DD;
    if (idx >= BB * nper) return;
    int b = idx / nper;
    int r = idx % nper;
    size_t o = ((size_t)b*SPD + MSEQ) * DD + r;
    g_h[o] = 0.f;
    g_hh[o] = __float2half_rn(0.f);
}

__global__ void out_proj(const float* __restrict__ Ws, const float* __restrict__ bs,
                         float* __restrict__ out)
{
    int idx = blockIdx.x * 256 + threadIdx.x;
    if (idx >= BB * MSEQ * 16) return;
    int j = idx & 15;
    int s = (idx >> 4) & 1023;
    int b = idx >> 14;
    const float* hr = g_h + ((size_t)b*SPD + s) * DD;
    float acc = bs[j];
    for (int d = 0; d < DD; d++) acc += hr[d] * Ws[d*16 + j];
    out[idx] = acc;
}

__global__ void elbo_fin(float* out, int out_size)
{
    if (threadIdx.x == 0 && out_size > BB*MSEQ*16) {
        float s = 0.f;
        for (int i = 0; i < BB; i++) s += g_elbo_b[i];
        out[BB*MSEQ*16] = s * (1.f / BB);
    }
}

// ---------------- launch ----------------
extern "C" void kernel_launch(void* const* d_in, const int* in_sizes, int n_in,
                              void* d_out, int out_size)
{
    const float* x       = (const float*)d_in[0];
    const float* eps     = (const float*)d_in[1];
    const float* emb_in  = (const float*)d_in[2];
    const float* emb_out = (const float*)d_in[3];
    const float* W_data  = (const float*)d_in[4];
    const float* b_data  = (const float*)d_in[5];
    const float* Wqkv    = (const float*)d_in[6];
    const float* bqkv    = (const float*)d_in[7];
    const float* Wo      = (const float*)d_in[8];
    const float* bo      = (const float*)d_in[9];
    const float* ln1_g   = (const float*)d_in[10];
    const float* ln1_b   = (const float*)d_in[11];
    const float* W1      = (const float*)d_in[12];
    const float* b1      = (const float*)d_in[13];
    const float* W2      = (const float*)d_in[14];
    const float* b2      = (const float*)d_in[15];
    const float* ln2_g   = (const float*)d_in[16];
    const float* ln2_b   = (const float*)d_in[17];
    const float* W_mean  = (const float*)d_in[18];
    const float* b_mean  = (const float*)d_in[19];
    const float* W_lv    = (const float*)d_in[20];
    const float* b_lv    = (const float*)d_in[21];
    const float* W_exp   = (const float*)d_in[22];
    const float* b_exp   = (const float*)d_in[23];
    const float* W_conv  = (const float*)d_in[24];
    const float* b_conv  = (const float*)d_in[25];
    const float* W_seq   = (const float*)d_in[26];
    const float* b_seq   = (const float*)d_in[27];
    const int*   rand_enc= (const int*)d_in[28];
    const int*   rand_dec= (const int*)d_in[29];

    float *h_;
    __half *hh_, *qkvh_, *atth_, *tmph_, *ffh_, *wb_;
    cudaGetSymbolAddress((void**)&h_,    g_h);
    cudaGetSymbolAddress((void**)&hh_,   g_hh);
    cudaGetSymbolAddress((void**)&qkvh_, g_qkvh);
    cudaGetSymbolAddress((void**)&atth_, g_atth);
    cudaGetSymbolAddress((void**)&tmph_, g_tmph);
    cudaGetSymbolAddress((void**)&ffh_,  g_ffh);
    cudaGetSymbolAddress((void**)&wb_,   g_wb);

    cudaFuncSetAttribute(gemm_tc, cudaFuncAttributeMaxDynamicSharedMemorySize, SMEM_GEMM);

    const int M = MTOT;

    wconv<<<dim3(1536/32, 512/32, 10), dim3(32,8)>>>(Wqkv, wb_,
        512, 1536, (size_t)512*1536, WB_PER_LAYER);
    wconv<<<dim3(512/32, 512/32, 10), dim3(32,8)>>>(Wo, wb_ + 786432,
        512, 512, (size_t)512*512, WB_PER_LAYER);
    wconv<<<dim3(2048/32, 512/32, 10), dim3(32,8)>>>(W1, wb_ + 1048576,
        512, 2048, (size_t)512*2048, WB_PER_LAYER);
    wconv<<<dim3(512/32, 2048/32, 10), dim3(32,8)>>>(W2, wb_ + 2097152,
        2048, 512, (size_t)2048*512, WB_PER_LAYER);

    embed_enc<<<(BB*SPD*DD + 255)/256, 256>>>(x, W_data, b_data, emb_in);

    for (int i = 0; i < 10; i++) {
        const int* rnd = (i < 5) ? rand_enc : rand_dec;
        int nb = (i < 5) ? 129 : 128;
        int S  = (i < 5) ? 1025 : 1024;
        size_t L = (size_t)i * WB_PER_LAYER;

        gemm_tc<<<dim3(12, M/128), 256, SMEM_GEMM>>>(hh_, wb_ + L,
            bqkv + (size_t)i*1536, qkvh_, 1536, 512, 2);
        attn_kernel<<<dim3(nb, HH, BB), 256>>>(qkvh_, atth_, rnd, nb, S);
        gemm_tc<<<dim3(4, M/128), 256, SMEM_GEMM>>>(atth_, wb_ + L + 786432,
            bo + (size_t)i*512, tmph_, 512, 512, 2);
        add_ln<<<M/8, 256>>>(h_, hh_, tmph_, ln1_g + (size_t)i*DD, ln1_b + (size_t)i*DD);
        gemm_tc<<<dim3(16, M/128), 256, SMEM_GEMM>>>(hh_, wb_ + L + 1048576,
            b1 + (size_t)i*FFD, ffh_, 2048, 512, 1);
        gemm_tc<<<dim3(4, M/128), 256, SMEM_GEMM>>>(ffh_, wb_ + L + 2097152,
            b2 + (size_t)i*512, tmph_, 512, 2048, 2);
        add_ln<<<M/8, 256>>>(h_, hh_, tmph_, ln2_g + (size_t)i*DD, ln2_b + (size_t)i*DD);

        if (i == 4) {
            latent<<<BB, 16>>>(W_mean, b_mean, W_lv, b_lv, eps);
            seq_expand<<<(BB*2*MSEQ + 255)/256, 256>>>(W_exp, b_exp);
            dec_init<<<(BB*MSEQ*DD + 255)/256, 256>>>(W_conv, b_conv, emb_out);
            zero_pad_rows<<<(BB*(SPD-MSEQ)*DD + 255)/256, 256>>>();
        }
    }

    out_proj<<<(BB*MSEQ*16 + 255)/256, 256>>>(W_seq, b_seq, (float*)d_out);
    elbo_fin<<<1, 32>>>((float*)d_out, out_size);
}